// round 1
// baseline (speedup 1.0000x reference)
#include <cuda_runtime.h>
#include <cuda_bf16.h>

// Quantize_8881992368326 — VQ-VAE eval forward.
// x: [32,64,64,64] f32  -> N=131072 rows of DIM=64
// embed: [DIM=64, NE=512] f32 (codebook, dim-major)
// Outputs (flattened, f32): quantize[N*DIM] | diff[1] | embed_ind[N] (as float)

#define DIM   64
#define NE    512
#define NROWS (32*64*64)   /* 131072 */
#define GRID  148
#define TPB   512

__device__ float g_partials[GRID];

__global__ __launch_bounds__(TPB, 1)
void vq_kernel(const float* __restrict__ x,
               const float* __restrict__ embed,
               float* __restrict__ out_q,
               float* __restrict__ out_idx)
{
    extern __shared__ float smem[];
    float* se    = smem;             // [NE*DIM], code-major: se[j*DIM + k]
    float* snorm = smem + NE * DIM;  // [NE]
    __shared__ float sred[TPB / 32];

    const int tid = threadIdx.x;

    // Load + transpose codebook: embed[k*NE + j] -> se[j*DIM + k].
    // (One-time; bank conflicts on the strided STS are negligible vs mainloop.)
    for (int i = tid; i < DIM * NE; i += TPB) {
        int k = i / NE;
        int j = i - k * NE;
        se[j * DIM + k] = embed[i];
    }
    __syncthreads();

    // Precompute ||e_j||^2
    for (int j = tid; j < NE; j += TPB) {
        const float* e = se + j * DIM;
        float s = 0.f;
        #pragma unroll
        for (int k = 0; k < DIM; k++) s = fmaf(e[k], e[k], s);
        snorm[j] = s;
    }
    __syncthreads();

    // Row range for this block
    const int rowsPer = (NROWS + GRID - 1) / GRID;
    const int r0 = blockIdx.x * rowsPer;
    const int r1 = min(r0 + rowsPer, NROWS);

    float ldiff = 0.f;

    for (int row = r0 + tid; row < r1; row += TPB) {
        // Load this row into registers (16x LDG.128)
        float f[DIM];
        const float4* xr = (const float4*)(x + (size_t)row * DIM);
        #pragma unroll
        for (int v = 0; v < DIM / 4; v++) {
            float4 t = xr[v];
            f[4*v+0] = t.x; f[4*v+1] = t.y; f[4*v+2] = t.z; f[4*v+3] = t.w;
        }

        // score_j = 2*(f . e_j) - ||e_j||^2 ; argmax == argmin dist.
        // First-index tie-break (strict >) matches jnp.argmax(-dist).
        float best = -3.402823466e38f;
        int   bi   = 0;
        for (int j = 0; j < NE; j++) {
            const float4* e = (const float4*)(se + j * DIM);
            float a0 = 0.f, a1 = 0.f, a2 = 0.f, a3 = 0.f;
            #pragma unroll
            for (int v = 0; v < DIM / 4; v++) {
                float4 t = e[v];          // broadcast LDS.128 — all lanes same j
                a0 = fmaf(f[4*v+0], t.x, a0);
                a1 = fmaf(f[4*v+1], t.y, a1);
                a2 = fmaf(f[4*v+2], t.z, a2);
                a3 = fmaf(f[4*v+3], t.w, a3);
            }
            float dot = (a0 + a1) + (a2 + a3);
            float s = fmaf(2.f, dot, -snorm[j]);
            if (s > best) { best = s; bi = j; }
        }

        // Gather winning code, write output, accumulate diff
        float4* qo = (float4*)(out_q + (size_t)row * DIM);
        const float4* e = (const float4*)(se + bi * DIM);
        #pragma unroll
        for (int v = 0; v < DIM / 4; v++) {
            float4 t = e[v];
            qo[v] = t;
            float d0 = t.x - f[4*v+0], d1 = t.y - f[4*v+1];
            float d2 = t.z - f[4*v+2], d3 = t.w - f[4*v+3];
            ldiff = fmaf(d0, d0, ldiff);
            ldiff = fmaf(d1, d1, ldiff);
            ldiff = fmaf(d2, d2, ldiff);
            ldiff = fmaf(d3, d3, ldiff);
        }
        out_idx[row] = (float)bi;
    }

    // Deterministic block reduction of ldiff (fixed shfl tree + fixed-order smem sum)
    #pragma unroll
    for (int o = 16; o > 0; o >>= 1)
        ldiff += __shfl_down_sync(0xffffffff, ldiff, o);
    if ((tid & 31) == 0) sred[tid >> 5] = ldiff;
    __syncthreads();
    if (tid == 0) {
        float s = 0.f;
        #pragma unroll
        for (int w = 0; w < TPB / 32; w++) s += sred[w];
        g_partials[blockIdx.x] = s;
    }
}

__global__ void finalize_kernel(float* __restrict__ out_diff)
{
    // Single thread, fixed-order sum over block partials -> deterministic.
    float s = 0.f;
    for (int i = 0; i < GRID; i++) s += g_partials[i];
    *out_diff = s * (1.0f / (float)(NROWS * DIM));
}

extern "C" void kernel_launch(void* const* d_in, const int* in_sizes, int n_in,
                              void* d_out, int out_size)
{
    const float* x     = (const float*)d_in[0];
    const float* embed = (const float*)d_in[1];

    float* out      = (float*)d_out;
    float* out_q    = out;                              // [N*DIM]
    float* out_diff = out + (size_t)NROWS * DIM;        // [1]
    float* out_idx  = out + (size_t)NROWS * DIM + 1;    // [N]

    size_t smem = (size_t)(NE * DIM + NE) * sizeof(float); // 133120 B
    cudaFuncSetAttribute(vq_kernel, cudaFuncAttributeMaxDynamicSharedMemorySize, (int)smem);

    vq_kernel<<<GRID, TPB, smem>>>(x, embed, out_q, out_idx);
    finalize_kernel<<<1, 1>>>(out_diff);
}

// round 3
// speedup vs baseline: 1.3198x; 1.3198x over previous
#include <cuda_runtime.h>
#include <cuda_bf16.h>
#include <cstdint>
#include <cfloat>

// Quantize_8881992368326 — VQ-VAE eval forward via mma.sync tf32 + exact fp32 refinement.
// (tcgen05 unavailable: harness compiles for plain sm_100, not sm_100a)
// x: [131072, 64] f32, embed: [64, 512] f32 (dim-major).
// out (f32): quantize[131072*64] | diff[1] | embed_ind[131072]

#define DIM     64
#define NE      512
#define NROWS   (32*64*64)        /* 131072 */
#define TILE_M  128
#define NTILES  (NROWS / TILE_M)  /* 1024 */
#define GRIDSZ  148
#define TPB     128
#define MARGIN  0.2f

// SMEM layout (bytes)
#define OFF_B     0                 /* 512 codes x 256B tf32, XOR-swizzled */
#define OFF_NORM  131072            /* 512 f32 */
#define OFF_CMAX  133120            /* 128 rows x 8 chunks f32 (HMMA chunk maxima) */
#define OFF_WIDX  137216            /* 128 int */
#define OFF_RED   137728            /* 4 f32 */
#define SMEM_TOTAL 137792

__device__ float g_cbT[NE * DIM];     // code-major fp32 codebook
__device__ float g_enorm[NE];         // ||e_j||^2 fp32
__device__ float g_tpart[NTILES];     // per-tile diff partials

__device__ __forceinline__ uint32_t f2tf32(float f) {
    uint32_t r;
    asm("cvt.rna.tf32.f32 %0, %1;" : "=r"(r) : "f"(f));
    return r;
}
__device__ __forceinline__ void mma_tf32(float& c0, float& c1, float& c2, float& c3,
                                         uint32_t a0, uint32_t a1, uint32_t a2, uint32_t a3,
                                         uint32_t b0, uint32_t b1) {
    asm volatile("mma.sync.aligned.m16n8k8.row.col.f32.tf32.tf32.f32 "
                 "{%0,%1,%2,%3}, {%4,%5,%6,%7}, {%8,%9}, {%0,%1,%2,%3};"
                 : "+f"(c0), "+f"(c1), "+f"(c2), "+f"(c3)
                 : "r"(a0), "r"(a1), "r"(a2), "r"(a3), "r"(b0), "r"(b1));
}

// ---------------- prep: transpose codebook + norms ----------------
__global__ void prep_kernel(const float* __restrict__ embed) {
    int j = blockIdx.x * blockDim.x + threadIdx.x;
    if (j < NE) {
        float n = 0.f;
        #pragma unroll
        for (int k = 0; k < DIM; k++) {
            float v = embed[k * NE + j];
            g_cbT[j * DIM + k] = v;
            n = fmaf(v, v, n);
        }
        g_enorm[j] = n;
    }
}

// ---------------- main kernel ----------------
__global__ __launch_bounds__(TPB, 1)
void vq_kernel(const float* __restrict__ x,
               float* __restrict__ out_q,
               float* __restrict__ out_idx)
{
    extern __shared__ char smem[];
    float* snorm_s = (float*)(smem + OFF_NORM);
    float* scmax   = (float*)(smem + OFF_CMAX);
    int*   swidx   = (int*)(smem + OFF_WIDX);
    float* sred    = (float*)(smem + OFF_RED);

    const int tid  = threadIdx.x;
    const int lane = tid & 31;
    const int wid  = tid >> 5;
    const int gid  = lane >> 2;   // 0..7
    const int tig  = lane & 3;    // 0..3

    // Fill swizzled tf32 codebook + norms
    for (int i = tid; i < NE * DIM; i += TPB) {
        int j = i >> 6, k = i & 63;
        uint32_t v = f2tf32(g_cbT[j * DIM + k]);
        *(uint32_t*)(smem + OFF_B + j * 256 + ((k * 4) ^ ((j & 7) << 5))) = v;
    }
    for (int i = tid; i < NE; i += TPB) snorm_s[i] = g_enorm[i];
    __syncthreads();

    for (int t = blockIdx.x; t < NTILES; t += GRIDSZ) {
        const int base_row = t * TILE_M + wid * 32;

        // ---- Load A fragments (tf32) for 2 m16-tiles x 8 k-steps
        uint32_t af[2][8][4];
        #pragma unroll
        for (int m = 0; m < 2; m++) {
            const float* xr  = x + (size_t)(base_row + m * 16 + gid) * DIM;
            const float* xr8 = xr + 8 * DIM;
            #pragma unroll
            for (int ks = 0; ks < 8; ks++) {
                int c = ks * 8 + tig;
                af[m][ks][0] = f2tf32(xr[c]);
                af[m][ks][1] = f2tf32(xr8[c]);
                af[m][ks][2] = f2tf32(xr[c + 4]);
                af[m][ks][3] = f2tf32(xr8[c + 4]);
            }
        }

        // per-row-state: [m][h] h=0: row gid, h=1: row gid+8
        float b1v[2][2], b2v[2][2]; int i1v[2][2];
        #pragma unroll
        for (int m = 0; m < 2; m++)
            #pragma unroll
            for (int h = 0; h < 2; h++) { b1v[m][h] = -FLT_MAX; b2v[m][h] = -FLT_MAX; i1v[m][h] = 0; }

        #pragma unroll 1
        for (int chunk = 0; chunk < 8; chunk++) {
            float acc[2][8][4];
            #pragma unroll
            for (int m = 0; m < 2; m++)
                #pragma unroll
                for (int nt = 0; nt < 8; nt++)
                    #pragma unroll
                    for (int q = 0; q < 4; q++) acc[m][nt][q] = 0.f;

            const char* bbase = smem + OFF_B + (size_t)chunk * 64 * 256 + gid * 256 + tig * 4;
            #pragma unroll
            for (int ks = 0; ks < 8; ks++) {
                #pragma unroll
                for (int nt = 0; nt < 8; nt++) {
                    const char* ba = bbase + nt * 2048 + (((unsigned)(ks ^ gid)) << 5);
                    uint32_t b0 = *(const uint32_t*)(ba);
                    uint32_t b1 = *(const uint32_t*)(ba + 16);
                    mma_tf32(acc[0][nt][0], acc[0][nt][1], acc[0][nt][2], acc[0][nt][3],
                             af[0][ks][0], af[0][ks][1], af[0][ks][2], af[0][ks][3], b0, b1);
                    mma_tf32(acc[1][nt][0], acc[1][nt][1], acc[1][nt][2], acc[1][nt][3],
                             af[1][ks][0], af[1][ks][1], af[1][ks][2], af[1][ks][3], b0, b1);
                }
            }

            // ---- chunk epilogue: scores + top2 + chunk max
            float cmq[2][2];
            #pragma unroll
            for (int m = 0; m < 2; m++)
                #pragma unroll
                for (int h = 0; h < 2; h++) cmq[m][h] = -FLT_MAX;

            #pragma unroll
            for (int nt = 0; nt < 8; nt++) {
                int n0 = chunk * 64 + nt * 8;
                float2 nrm = *(const float2*)(snorm_s + n0 + 2 * tig);
                int j0 = n0 + 2 * tig;
                #pragma unroll
                for (int m = 0; m < 2; m++) {
                    #pragma unroll
                    for (int h = 0; h < 2; h++) {
                        float s0 = fmaf(2.f, acc[m][nt][h * 2 + 0], -nrm.x);
                        float s1 = fmaf(2.f, acc[m][nt][h * 2 + 1], -nrm.y);
                        if (s0 > b1v[m][h]) { b2v[m][h] = b1v[m][h]; b1v[m][h] = s0; i1v[m][h] = j0; }
                        else if (s0 > b2v[m][h]) b2v[m][h] = s0;
                        if (s1 > b1v[m][h]) { b2v[m][h] = b1v[m][h]; b1v[m][h] = s1; i1v[m][h] = j0 + 1; }
                        else if (s1 > b2v[m][h]) b2v[m][h] = s1;
                        float mx = fmaxf(s0, s1);
                        if (mx > cmq[m][h]) cmq[m][h] = mx;
                    }
                }
            }
            // quad-reduce chunk max, store to smem (per row)
            #pragma unroll
            for (int m = 0; m < 2; m++)
                #pragma unroll
                for (int h = 0; h < 2; h++) {
                    float v = cmq[m][h];
                    v = fmaxf(v, __shfl_xor_sync(0xffffffffu, v, 1));
                    v = fmaxf(v, __shfl_xor_sync(0xffffffffu, v, 2));
                    if (tig == 0) scmax[(wid * 32 + m * 16 + h * 8 + gid) * 8 + chunk] = v;
                }
        }

        // ---- quad-reduce top2 states
        #pragma unroll
        for (int m = 0; m < 2; m++)
            #pragma unroll
            for (int h = 0; h < 2; h++) {
                #pragma unroll
                for (int off = 1; off <= 2; off <<= 1) {
                    float ob1 = __shfl_xor_sync(0xffffffffu, b1v[m][h], off);
                    int   oi1 = __shfl_xor_sync(0xffffffffu, i1v[m][h], off);
                    float ob2 = __shfl_xor_sync(0xffffffffu, b2v[m][h], off);
                    if (ob1 > b1v[m][h] || (ob1 == b1v[m][h] && oi1 < i1v[m][h])) {
                        b2v[m][h] = fmaxf(b1v[m][h], ob2);
                        b1v[m][h] = ob1; i1v[m][h] = oi1;
                    } else {
                        b2v[m][h] = fmaxf(b2v[m][h], ob1);
                    }
                }
            }

        __syncwarp();

        // ---- fallback: exact rescoring of ambiguous rows (warp-cooperative)
        #pragma unroll
        for (int m = 0; m < 2; m++) {
            #pragma unroll
            for (int h = 0; h < 2; h++) {
                bool need = (b1v[m][h] - b2v[m][h]) < MARGIN;
                unsigned mask = __ballot_sync(0xffffffffu, need && tig == 0);
                while (mask) {
                    int l = __ffs(mask) - 1; mask &= mask - 1;
                    int g = l >> 2;
                    int rl = wid * 32 + m * 16 + h * 8 + g;
                    int grow = t * TILE_M + rl;
                    float thr = __shfl_sync(0xffffffffu, b1v[m][h], l) - MARGIN;
                    const float4* xr4 = (const float4*)(x + (size_t)grow * DIM);

                    int cand[6]; int nc = 0;
                    for (int ch = 0; ch < 8; ch++) {
                        if (scmax[rl * 8 + ch] < thr) continue;
                        #pragma unroll
                        for (int half = 0; half < 2; half++) {
                            int j = ch * 64 + half * 32 + lane;
                            float d0 = 0.f, d1 = 0.f, d2 = 0.f, d3 = 0.f;
                            #pragma unroll
                            for (int v = 0; v < 16; v++) {
                                float4 ev = *(const float4*)(smem + OFF_B + j * 256 +
                                                             ((v * 16) ^ ((lane & 7) << 5)));
                                float4 fv = xr4[v];
                                d0 = fmaf(fv.x, ev.x, d0); d1 = fmaf(fv.y, ev.y, d1);
                                d2 = fmaf(fv.z, ev.z, d2); d3 = fmaf(fv.w, ev.w, d3);
                            }
                            float sa = fmaf(2.f, (d0 + d1) + (d2 + d3), -snorm_s[j]);
                            if (sa >= thr && nc < 6) cand[nc++] = j;
                        }
                    }
                    // exact fp32 rescore of candidates (same associativity as round-1)
                    float bw = -FLT_MAX; int wj = 0x7fffffff;
                    for (int i = 0; i < nc; i++) {
                        int j = cand[i];
                        const float4* er4 = (const float4*)(g_cbT + j * DIM);
                        float a0 = 0.f, a1 = 0.f, a2 = 0.f, a3 = 0.f;
                        #pragma unroll
                        for (int v = 0; v < 16; v++) {
                            float4 fv = xr4[v]; float4 ev = er4[v];
                            a0 = fmaf(fv.x, ev.x, a0); a1 = fmaf(fv.y, ev.y, a1);
                            a2 = fmaf(fv.z, ev.z, a2); a3 = fmaf(fv.w, ev.w, a3);
                        }
                        float s = fmaf(2.f, (a0 + a1) + (a2 + a3), -g_enorm[j]);
                        if (s > bw || (s == bw && j < wj)) { bw = s; wj = j; }
                    }
                    // warp-reduce (bw, wj)
                    #pragma unroll
                    for (int off = 16; off > 0; off >>= 1) {
                        float ob = __shfl_xor_sync(0xffffffffu, bw, off);
                        int   oj = __shfl_xor_sync(0xffffffffu, wj, off);
                        if (ob > bw || (ob == bw && oj < wj)) { bw = ob; wj = oj; }
                    }
                    if (lane == l) i1v[m][h] = wj;
                }
            }
        }

        // write winners
        #pragma unroll
        for (int m = 0; m < 2; m++)
            #pragma unroll
            for (int h = 0; h < 2; h++)
                if (tig == 0) swidx[wid * 32 + m * 16 + h * 8 + gid] = i1v[m][h];
        __syncthreads();

        // ---- output gather + exact diff
        const float4* cb4 = (const float4*)g_cbT;
        float4* oq = (float4*)(out_q + (size_t)t * TILE_M * DIM);
        const float4* xin = (const float4*)(x + (size_t)t * TILE_M * DIM);
        float td = 0.f;
        #pragma unroll
        for (int it = 0; it < (TILE_M * 16) / TPB; it++) {
            int i = tid + it * TPB;
            int row = i >> 4, v = i & 15;
            float4 e = cb4[swidx[row] * 16 + v];
            float4 xv = xin[i];
            oq[i] = e;
            float d0 = e.x - xv.x, d1 = e.y - xv.y, d2 = e.z - xv.z, d3 = e.w - xv.w;
            td = fmaf(d0, d0, td); td = fmaf(d1, d1, td);
            td = fmaf(d2, d2, td); td = fmaf(d3, d3, td);
        }
        out_idx[(size_t)t * TILE_M + tid] = (float)swidx[tid];

        // per-tile deterministic reduction
        #pragma unroll
        for (int off = 16; off > 0; off >>= 1)
            td += __shfl_down_sync(0xffffffffu, td, off);
        if (lane == 0) sred[wid] = td;
        __syncthreads();
        if (tid == 0) g_tpart[t] = (sred[0] + sred[1]) + (sred[2] + sred[3]);
        __syncthreads();
    }
}

__global__ void finalize_kernel(float* __restrict__ out_diff) {
    __shared__ float s[128];
    int tid = threadIdx.x;
    float v = 0.f;
    for (int i = tid; i < NTILES; i += 128) v += g_tpart[i];
    s[tid] = v;
    __syncthreads();
    for (int o = 64; o > 0; o >>= 1) {
        if (tid < o) s[tid] += s[tid + o];
        __syncthreads();
    }
    if (tid == 0) *out_diff = s[0] * (1.0f / (float)((size_t)NROWS * DIM));
}

extern "C" void kernel_launch(void* const* d_in, const int* in_sizes, int n_in,
                              void* d_out, int out_size)
{
    const float* x     = (const float*)d_in[0];
    const float* embed = (const float*)d_in[1];

    float* out      = (float*)d_out;
    float* out_q    = out;
    float* out_diff = out + (size_t)NROWS * DIM;
    float* out_idx  = out + (size_t)NROWS * DIM + 1;

    cudaFuncSetAttribute(vq_kernel, cudaFuncAttributeMaxDynamicSharedMemorySize, SMEM_TOTAL);

    prep_kernel<<<2, 256>>>(embed);
    vq_kernel<<<GRIDSZ, TPB, SMEM_TOTAL>>>(x, out_q, out_idx);
    finalize_kernel<<<1, 128>>>(out_diff);
}

// round 4
// speedup vs baseline: 3.4021x; 2.5778x over previous
#include <cuda_runtime.h>
#include <cuda_fp16.h>
#include <cstdint>
#include <cfloat>

// Quantize_8881992368326 — VQ-VAE eval forward.
// mma.sync m16n8k16 f16 (fp32 accum) + branch-free keyed argmax + exact fp32 fallback.
// x: [131072, 64] f32, embed: [64, 512] f32 (dim-major).
// out (f32): quantize[131072*64] | diff[1] | embed_ind[131072]

#define DIM     64
#define NE      512
#define NROWS   (32*64*64)
#define TILE_M  128
#define NTILES  (NROWS / TILE_M)   /* 1024 */
#define GRIDSZ  148
#define TPB     256
#define MARGIN  0.4f
#define CBS     68                 /* fp32 codebook row stride (floats), pad for banks */

// SMEM layout (bytes)
#define OFF_B      0                         /* f16 B: 512 codes x 128B, swizzled */
#define OFF_NORM   65536                     /* 512 f32 */
#define OFF_CB     67584                     /* fp32 codebook 512 x CBS */
#define OFF_SCMAX  (OFF_CB + NE*CBS*4)       /* 128 rows x 8 chunk-max f32 */
#define OFF_WIDX   (OFF_SCMAX + TILE_M*8*4)  /* 128 int */
#define OFF_RED    (OFF_WIDX + TILE_M*4)     /* 8 f32 */
#define SMEM_TOTAL (OFF_RED + 64)            /* ~211.5 KB */

__device__ float g_tpart[NTILES];

__device__ __forceinline__ uint32_t f2h2(float lo, float hi) {
    uint32_t r;
    asm("cvt.rn.f16x2.f32 %0, %1, %2;" : "=r"(r) : "f"(hi), "f"(lo)); // %1 -> upper half
    return r;
}
__device__ __forceinline__ void mma_f16(float& c0, float& c1, float& c2, float& c3,
                                        uint32_t a0, uint32_t a1, uint32_t a2, uint32_t a3,
                                        uint32_t b0, uint32_t b1) {
    asm volatile("mma.sync.aligned.m16n8k16.row.col.f32.f16.f16.f32 "
                 "{%0,%1,%2,%3}, {%4,%5,%6,%7}, {%8,%9}, {%0,%1,%2,%3};"
                 : "+f"(c0), "+f"(c1), "+f"(c2), "+f"(c3)
                 : "r"(a0), "r"(a1), "r"(a2), "r"(a3), "r"(b0), "r"(b1));
}
// float -> sortable uint, idx packed in low 9 bits (idxc = 511 - j; bigger = smaller j)
__device__ __forceinline__ uint32_t skey(float s, uint32_t idxc) {
    int i = __float_as_int(s);
    uint32_t u = (uint32_t)(i ^ ((i >> 31) | 0x80000000));
    return (u & 0xfffffe00u) | idxc;
}
__device__ __forceinline__ float keyf(uint32_t k) {
    uint32_t u = k & 0xfffffe00u;
    int i = (u & 0x80000000u) ? (int)(u ^ 0x80000000u) : ~(int)u;
    return __int_as_float(i);
}
__device__ __forceinline__ void upd(uint32_t& m1, uint32_t& m2, uint32_t& cm, uint32_t k) {
    cm = max(cm, k);
    m2 = max(m2, min(m1, k));
    m1 = max(m1, k);
}

__global__ __launch_bounds__(TPB, 1)
void vq_kernel(const float* __restrict__ x,
               const float* __restrict__ embed,
               float* __restrict__ out_q,
               float* __restrict__ out_idx)
{
    extern __shared__ char smem[];
    float* cbf     = (float*)(smem + OFF_CB);
    float* snorm   = (float*)(smem + OFF_NORM);
    float* scmaxf  = (float*)(smem + OFF_SCMAX);
    int*   swidx   = (int*)(smem + OFF_WIDX);
    float* sred    = (float*)(smem + OFF_RED);

    const int tid  = threadIdx.x;
    const int lane = tid & 31;
    const int wid  = tid >> 5;
    const int gid  = lane >> 2;   // 0..7
    const int tig  = lane & 3;    // 0..3

    // ---- build smem: fp32 codebook (transposed), norms, f16 B (swizzled) ----
    for (int i = tid; i < DIM * NE; i += TPB) {       // coalesced read of embed
        int k = i >> 9, j = i & 511;
        cbf[j * CBS + k] = embed[i];
    }
    __syncthreads();
    for (int j = tid; j < NE; j += TPB) {
        const float* e = cbf + j * CBS;
        float n = 0.f;
        #pragma unroll
        for (int k = 0; k < DIM; k++) n = fmaf(e[k], e[k], n);
        snorm[j] = n;
    }
    for (int i = tid; i < NE * 32; i += TPB) {        // 32 f16x2 pairs per code
        int j = i >> 5, p = i & 31;
        int blk = p >> 3, s = p & 7;
        int P = (s >> 1) + ((s & 1) << 2);            // pair index within k16 block
        int k = blk * 16 + P * 2;
        uint32_t h2 = f2h2(cbf[j * CBS + k], cbf[j * CBS + k + 1]);
        uint32_t off = (uint32_t)(j * 128) + (((uint32_t)(blk * 32 + s * 4)) ^ (((uint32_t)(j & 3)) << 5));
        *(uint32_t*)(smem + OFF_B + off) = h2;
    }
    __syncthreads();

    const uint32_t bsw = ((uint32_t)(gid & 3)) << 5;  // (j&3)<<5 is constant per thread

    for (int t = blockIdx.x; t < NTILES; t += GRIDSZ) {
        const int rowbase = t * TILE_M + wid * 16;

        // ---- A fragments: rows gid & gid+8, k16 x 4 steps
        uint32_t a[4][4];
        {
            const float* xr0 = x + (size_t)(rowbase + gid) * DIM;
            const float* xr8 = xr0 + 8 * DIM;
            #pragma unroll
            for (int ks = 0; ks < 4; ks++) {
                float2 p;
                p = *(const float2*)(xr0 + ks * 16 + 2 * tig);     a[ks][0] = f2h2(p.x, p.y);
                p = *(const float2*)(xr8 + ks * 16 + 2 * tig);     a[ks][1] = f2h2(p.x, p.y);
                p = *(const float2*)(xr0 + ks * 16 + 2 * tig + 8); a[ks][2] = f2h2(p.x, p.y);
                p = *(const float2*)(xr8 + ks * 16 + 2 * tig + 8); a[ks][3] = f2h2(p.x, p.y);
            }
        }

        uint32_t m1[2] = {0u, 0u}, m2[2] = {0u, 0u};

        #pragma unroll 1
        for (int chunk = 0; chunk < 8; chunk++) {
            float acc[8][4];
            #pragma unroll
            for (int nt = 0; nt < 8; nt++)
                #pragma unroll
                for (int q = 0; q < 4; q++) acc[nt][q] = 0.f;

            const int jrow0 = chunk * 64 + gid;       // this lane's B code for nt=0
            #pragma unroll
            for (int ks = 0; ks < 4; ks++) {
                #pragma unroll
                for (int nt = 0; nt < 8; nt++) {
                    uint32_t off = (uint32_t)((jrow0 + nt * 8) * 128) +
                                   (((uint32_t)(ks * 32 + tig * 8)) ^ bsw);
                    uint2 b = *(const uint2*)(smem + OFF_B + off);
                    mma_f16(acc[nt][0], acc[nt][1], acc[nt][2], acc[nt][3],
                            a[ks][0], a[ks][1], a[ks][2], a[ks][3], b.x, b.y);
                }
            }

            // ---- branch-free epilogue
            uint32_t cm[2] = {0u, 0u};
            const int jb = chunk * 64 + 2 * tig;
            #pragma unroll
            for (int nt = 0; nt < 8; nt++) {
                float2 nrm = *(const float2*)(snorm + jb + nt * 8);
                uint32_t ic0 = (uint32_t)(511 - (jb + nt * 8));
                uint32_t ic1 = ic0 - 1;
                float s;
                s = fmaf(2.f, acc[nt][0], -nrm.x); upd(m1[0], m2[0], cm[0], skey(s, ic0));
                s = fmaf(2.f, acc[nt][1], -nrm.y); upd(m1[0], m2[0], cm[0], skey(s, ic1));
                s = fmaf(2.f, acc[nt][2], -nrm.x); upd(m1[1], m2[1], cm[1], skey(s, ic0));
                s = fmaf(2.f, acc[nt][3], -nrm.y); upd(m1[1], m2[1], cm[1], skey(s, ic1));
            }
            #pragma unroll
            for (int h = 0; h < 2; h++) {
                uint32_t v = cm[h];
                v = max(v, __shfl_xor_sync(0xffffffffu, v, 1));
                v = max(v, __shfl_xor_sync(0xffffffffu, v, 2));
                if (tig == 0) scmaxf[(wid * 16 + h * 8 + gid) * 8 + chunk] = keyf(v);
            }
        }

        // ---- quad merge of (m1, m2)
        #pragma unroll
        for (int h = 0; h < 2; h++) {
            #pragma unroll
            for (int off = 1; off <= 2; off <<= 1) {
                uint32_t om1 = __shfl_xor_sync(0xffffffffu, m1[h], off);
                uint32_t om2 = __shfl_xor_sync(0xffffffffu, m2[h], off);
                uint32_t lo = min(m1[h], om1);
                m1[h] = max(m1[h], om1);
                m2[h] = max(max(m2[h], om2), lo);
            }
        }

        int jwin[2]; float bestf[2], gapf[2];
        #pragma unroll
        for (int h = 0; h < 2; h++) {
            jwin[h] = 511 - (int)(m1[h] & 511u);
            bestf[h] = keyf(m1[h]);
            gapf[h] = bestf[h] - keyf(m2[h]);
        }

        // ---- exact fp32 fallback for ambiguous rows (warp-cooperative, rare)
        #pragma unroll 1
        for (int h = 0; h < 2; h++) {
            unsigned mask = __ballot_sync(0xffffffffu, (tig == 0) && (gapf[h] < MARGIN));
            while (mask) {
                int l = __ffs(mask) - 1; mask &= mask - 1;
                int g = l >> 2;
                int lrow = wid * 16 + h * 8 + g;
                float thr = __shfl_sync(0xffffffffu, bestf[h], l) - MARGIN;
                const float4* xr4 = (const float4*)(x + (size_t)(t * TILE_M + lrow) * DIM);

                float bw = -FLT_MAX; int wj = NE;
                for (int ch = 0; ch < 8; ch++) {
                    if (scmaxf[lrow * 8 + ch] < thr) continue;
                    #pragma unroll
                    for (int half = 0; half < 2; half++) {
                        int j = ch * 64 + half * 32 + lane;
                        const float4* e4 = (const float4*)(cbf + j * CBS);
                        float d0 = 0.f, d1 = 0.f, d2 = 0.f, d3 = 0.f;
                        #pragma unroll
                        for (int v = 0; v < 16; v++) {
                            float4 fv = xr4[v]; float4 ev = e4[v];
                            d0 = fmaf(fv.x, ev.x, d0); d1 = fmaf(fv.y, ev.y, d1);
                            d2 = fmaf(fv.z, ev.z, d2); d3 = fmaf(fv.w, ev.w, d3);
                        }
                        float s = fmaf(2.f, (d0 + d1) + (d2 + d3), -snorm[j]);
                        if (s > bw || (s == bw && j < wj)) { bw = s; wj = j; }
                    }
                }
                #pragma unroll
                for (int off = 16; off > 0; off >>= 1) {
                    float ob = __shfl_xor_sync(0xffffffffu, bw, off);
                    int   oj = __shfl_xor_sync(0xffffffffu, wj, off);
                    if (ob > bw || (ob == bw && oj < wj)) { bw = ob; wj = oj; }
                }
                if (lane == l) jwin[h] = wj;
            }
        }

        if (tig == 0) {
            swidx[wid * 16 + gid]     = jwin[0];
            swidx[wid * 16 + 8 + gid] = jwin[1];
        }
        __syncthreads();

        // ---- output gather (from smem fp32 codebook) + exact diff
        const float4* xin = (const float4*)(x + (size_t)t * TILE_M * DIM);
        float4* oq = (float4*)(out_q + (size_t)t * TILE_M * DIM);
        const float4* cb4 = (const float4*)cbf;   // row stride 17 float4
        float td = 0.f;
        #pragma unroll
        for (int it = 0; it < (TILE_M * 16) / TPB; it++) {
            int i = tid + it * TPB;
            int row = i >> 4, v = i & 15;
            float4 e = cb4[swidx[row] * (CBS / 4) + v];
            float4 xv = xin[i];
            oq[i] = e;
            float d0 = e.x - xv.x, d1 = e.y - xv.y, d2 = e.z - xv.z, d3 = e.w - xv.w;
            td = fmaf(d0, d0, td); td = fmaf(d1, d1, td);
            td = fmaf(d2, d2, td); td = fmaf(d3, d3, td);
        }
        if (tid < TILE_M) out_idx[(size_t)t * TILE_M + tid] = (float)swidx[tid];

        #pragma unroll
        for (int off = 16; off > 0; off >>= 1)
            td += __shfl_down_sync(0xffffffffu, td, off);
        if (lane == 0) sred[wid] = td;
        __syncthreads();
        if (tid == 0) {
            float s = 0.f;
            #pragma unroll
            for (int w = 0; w < TPB / 32; w++) s += sred[w];
            g_tpart[t] = s;
        }
        __syncthreads();
    }
}

__global__ void finalize_kernel(float* __restrict__ out_diff) {
    __shared__ float s[128];
    int tid = threadIdx.x;
    float v = 0.f;
    for (int i = tid; i < NTILES; i += 128) v += g_tpart[i];
    s[tid] = v;
    __syncthreads();
    for (int o = 64; o > 0; o >>= 1) {
        if (tid < o) s[tid] += s[tid + o];
        __syncthreads();
    }
    if (tid == 0) *out_diff = s[0] * (1.0f / (float)((size_t)NROWS * DIM));
}

extern "C" void kernel_launch(void* const* d_in, const int* in_sizes, int n_in,
                              void* d_out, int out_size)
{
    const float* x     = (const float*)d_in[0];
    const float* embed = (const float*)d_in[1];

    float* out      = (float*)d_out;
    float* out_q    = out;
    float* out_diff = out + (size_t)NROWS * DIM;
    float* out_idx  = out + (size_t)NROWS * DIM + 1;

    cudaFuncSetAttribute(vq_kernel, cudaFuncAttributeMaxDynamicSharedMemorySize, SMEM_TOTAL);

    vq_kernel<<<GRIDSZ, TPB, SMEM_TOTAL>>>(x, embed, out_q, out_idx);
    finalize_kernel<<<1, 128>>>(out_diff);
}

// round 5
// speedup vs baseline: 3.4526x; 1.0149x over previous
#include <cuda_runtime.h>
#include <cuda_fp16.h>
#include <cstdint>
#include <cfloat>

// Quantize_8881992368326 — VQ-VAE eval forward.
// mma.sync m16n8k16 f16 (fp32 accum) + branch-free keyed argmax + exact fp32 fallback.
// Fused deterministic diff finalize (last-block pattern). 16 warps/CTA for latency hiding.
// x: [131072, 64] f32, embed: [64, 512] f32 (dim-major).
// out (f32): quantize[131072*64] | diff[1] | embed_ind[131072]

#define DIM     64
#define NE      512
#define NROWS   (32*64*64)
#define TILE_M  256
#define NTILES  (NROWS / TILE_M)   /* 512 */
#define GRIDSZ  148
#define TPB     512
#define NWARP   (TPB/32)
#define MARGIN  0.4f
#define CBS     68                 /* fp32 codebook row stride (floats), pad for banks */

// SMEM layout (bytes)
#define OFF_B      0                         /* f16 B: 512 codes x 128B, swizzled */
#define OFF_NORM   65536                     /* 512 f32 */
#define OFF_CB     67584                     /* fp32 codebook 512 x CBS */
#define OFF_SCMAX  (OFF_CB + NE*CBS*4)       /* 256 rows x 8 chunk-max f32 */
#define OFF_WIDX   (OFF_SCMAX + TILE_M*8*4)  /* 256 int */
#define OFF_RED    (OFF_WIDX + TILE_M*4)     /* 16 f32 */
#define SMEM_TOTAL (OFF_RED + NWARP*4)       /* ~216 KB */

__device__ float g_partials[GRIDSZ];
__device__ unsigned int g_done;              // zero-init; reset by last block each launch

__device__ __forceinline__ uint32_t f2h2(float lo, float hi) {
    uint32_t r;
    asm("cvt.rn.f16x2.f32 %0, %1, %2;" : "=r"(r) : "f"(hi), "f"(lo)); // %1 -> upper half
    return r;
}
__device__ __forceinline__ void mma_f16(float& c0, float& c1, float& c2, float& c3,
                                        uint32_t a0, uint32_t a1, uint32_t a2, uint32_t a3,
                                        uint32_t b0, uint32_t b1) {
    asm volatile("mma.sync.aligned.m16n8k16.row.col.f32.f16.f16.f32 "
                 "{%0,%1,%2,%3}, {%4,%5,%6,%7}, {%8,%9}, {%0,%1,%2,%3};"
                 : "+f"(c0), "+f"(c1), "+f"(c2), "+f"(c3)
                 : "r"(a0), "r"(a1), "r"(a2), "r"(a3), "r"(b0), "r"(b1));
}
// float -> sortable uint, idx packed in low 9 bits (idxc = 511 - j; bigger = smaller j)
__device__ __forceinline__ uint32_t skey(float s, uint32_t idxc) {
    int i = __float_as_int(s);
    uint32_t u = (uint32_t)(i ^ ((i >> 31) | 0x80000000));
    return (u & 0xfffffe00u) | idxc;
}
__device__ __forceinline__ float keyf(uint32_t k) {
    uint32_t u = k & 0xfffffe00u;
    int i = (u & 0x80000000u) ? (int)(u ^ 0x80000000u) : ~(int)u;
    return __int_as_float(i);
}
__device__ __forceinline__ void upd(uint32_t& m1, uint32_t& m2, uint32_t& cm, uint32_t k) {
    cm = max(cm, k);
    m2 = max(m2, min(m1, k));
    m1 = max(m1, k);
}

__global__ __launch_bounds__(TPB, 1)
void vq_kernel(const float* __restrict__ x,
               const float* __restrict__ embed,
               float* __restrict__ out_q,
               float* __restrict__ out_idx,
               float* __restrict__ out_diff)
{
    extern __shared__ char smem[];
    float* cbf    = (float*)(smem + OFF_CB);
    float* snorm  = (float*)(smem + OFF_NORM);
    float* scmaxf = (float*)(smem + OFF_SCMAX);
    int*   swidx  = (int*)(smem + OFF_WIDX);
    float* sred   = (float*)(smem + OFF_RED);

    const int tid  = threadIdx.x;
    const int lane = tid & 31;
    const int wid  = tid >> 5;
    const int gid  = lane >> 2;   // 0..7
    const int tig  = lane & 3;    // 0..3

    // ---- build smem: fp32 codebook (transposed), norms, f16 B (swizzled) ----
    for (int i = tid; i < DIM * NE; i += TPB) {       // coalesced read of embed
        int k = i >> 9, j = i & 511;
        cbf[j * CBS + k] = embed[i];
    }
    __syncthreads();
    for (int j = tid; j < NE; j += TPB) {
        const float* e = cbf + j * CBS;
        float n = 0.f;
        #pragma unroll
        for (int k = 0; k < DIM; k++) n = fmaf(e[k], e[k], n);
        snorm[j] = n;
    }
    for (int i = tid; i < NE * 32; i += TPB) {        // 32 f16x2 pairs per code
        int j = i >> 5, p = i & 31;
        int blk = p >> 3, s = p & 7;
        int P = (s >> 1) + ((s & 1) << 2);            // pair index within k16 block
        int k = blk * 16 + P * 2;
        uint32_t h2 = f2h2(cbf[j * CBS + k], cbf[j * CBS + k + 1]);
        uint32_t off = (uint32_t)(j * 128) + (((uint32_t)(blk * 32 + s * 4)) ^ (((uint32_t)(j & 3)) << 5));
        *(uint32_t*)(smem + OFF_B + off) = h2;
    }
    __syncthreads();

    const uint32_t bsw = ((uint32_t)(gid & 3)) << 5;  // (j&3)<<5 is constant per thread
    float blockdiff = 0.f;

    for (int t = blockIdx.x; t < NTILES; t += GRIDSZ) {
        const int rowbase = t * TILE_M + wid * 16;

        // ---- A fragments: rows gid & gid+8, k16 x 4 steps
        uint32_t a[4][4];
        {
            const float* xr0 = x + (size_t)(rowbase + gid) * DIM;
            const float* xr8 = xr0 + 8 * DIM;
            #pragma unroll
            for (int ks = 0; ks < 4; ks++) {
                float2 p;
                p = *(const float2*)(xr0 + ks * 16 + 2 * tig);     a[ks][0] = f2h2(p.x, p.y);
                p = *(const float2*)(xr8 + ks * 16 + 2 * tig);     a[ks][1] = f2h2(p.x, p.y);
                p = *(const float2*)(xr0 + ks * 16 + 2 * tig + 8); a[ks][2] = f2h2(p.x, p.y);
                p = *(const float2*)(xr8 + ks * 16 + 2 * tig + 8); a[ks][3] = f2h2(p.x, p.y);
            }
        }

        uint32_t m1[2] = {0u, 0u}, m2[2] = {0u, 0u};

        #pragma unroll 1
        for (int chunk = 0; chunk < 8; chunk++) {
            float acc[8][4];
            #pragma unroll
            for (int nt = 0; nt < 8; nt++)
                #pragma unroll
                for (int q = 0; q < 4; q++) acc[nt][q] = 0.f;

            const int jrow0 = chunk * 64 + gid;       // this lane's B code for nt=0
            #pragma unroll
            for (int ks = 0; ks < 4; ks++) {
                #pragma unroll
                for (int nt = 0; nt < 8; nt++) {
                    uint32_t off = (uint32_t)((jrow0 + nt * 8) * 128) +
                                   (((uint32_t)(ks * 32 + tig * 8)) ^ bsw);
                    uint2 b = *(const uint2*)(smem + OFF_B + off);
                    mma_f16(acc[nt][0], acc[nt][1], acc[nt][2], acc[nt][3],
                            a[ks][0], a[ks][1], a[ks][2], a[ks][3], b.x, b.y);
                }
            }

            // ---- branch-free epilogue
            uint32_t cm[2] = {0u, 0u};
            const int jb = chunk * 64 + 2 * tig;
            #pragma unroll
            for (int nt = 0; nt < 8; nt++) {
                float2 nrm = *(const float2*)(snorm + jb + nt * 8);
                uint32_t ic0 = (uint32_t)(511 - (jb + nt * 8));
                uint32_t ic1 = ic0 - 1;
                float s;
                s = fmaf(2.f, acc[nt][0], -nrm.x); upd(m1[0], m2[0], cm[0], skey(s, ic0));
                s = fmaf(2.f, acc[nt][1], -nrm.y); upd(m1[0], m2[0], cm[0], skey(s, ic1));
                s = fmaf(2.f, acc[nt][2], -nrm.x); upd(m1[1], m2[1], cm[1], skey(s, ic0));
                s = fmaf(2.f, acc[nt][3], -nrm.y); upd(m1[1], m2[1], cm[1], skey(s, ic1));
            }
            #pragma unroll
            for (int h = 0; h < 2; h++) {
                uint32_t v = cm[h];
                v = max(v, __shfl_xor_sync(0xffffffffu, v, 1));
                v = max(v, __shfl_xor_sync(0xffffffffu, v, 2));
                if (tig == 0) scmaxf[(wid * 16 + h * 8 + gid) * 8 + chunk] = keyf(v);
            }
        }

        // ---- quad merge of (m1, m2)
        #pragma unroll
        for (int h = 0; h < 2; h++) {
            #pragma unroll
            for (int off = 1; off <= 2; off <<= 1) {
                uint32_t om1 = __shfl_xor_sync(0xffffffffu, m1[h], off);
                uint32_t om2 = __shfl_xor_sync(0xffffffffu, m2[h], off);
                uint32_t lo = min(m1[h], om1);
                m1[h] = max(m1[h], om1);
                m2[h] = max(max(m2[h], om2), lo);
            }
        }

        int jwin[2]; float bestf[2], gapf[2];
        #pragma unroll
        for (int h = 0; h < 2; h++) {
            jwin[h] = 511 - (int)(m1[h] & 511u);
            bestf[h] = keyf(m1[h]);
            gapf[h] = bestf[h] - keyf(m2[h]);
        }

        __syncwarp();

        // ---- exact fp32 fallback for ambiguous rows (warp-cooperative, rare)
        #pragma unroll 1
        for (int h = 0; h < 2; h++) {
            unsigned mask = __ballot_sync(0xffffffffu, (tig == 0) && (gapf[h] < MARGIN));
            while (mask) {
                int l = __ffs(mask) - 1; mask &= mask - 1;
                int g = l >> 2;
                int lrow = wid * 16 + h * 8 + g;
                float thr = __shfl_sync(0xffffffffu, bestf[h], l) - MARGIN;
                const float4* xr4 = (const float4*)(x + (size_t)(t * TILE_M + lrow) * DIM);

                float bw = -FLT_MAX; int wj = NE;
                for (int ch = 0; ch < 8; ch++) {
                    if (scmaxf[lrow * 8 + ch] < thr) continue;
                    #pragma unroll
                    for (int half = 0; half < 2; half++) {
                        int j = ch * 64 + half * 32 + lane;
                        const float4* e4 = (const float4*)(cbf + j * CBS);
                        float d0 = 0.f, d1 = 0.f, d2 = 0.f, d3 = 0.f;
                        #pragma unroll
                        for (int v = 0; v < 16; v++) {
                            float4 fv = xr4[v]; float4 ev = e4[v];
                            d0 = fmaf(fv.x, ev.x, d0); d1 = fmaf(fv.y, ev.y, d1);
                            d2 = fmaf(fv.z, ev.z, d2); d3 = fmaf(fv.w, ev.w, d3);
                        }
                        float s = fmaf(2.f, (d0 + d1) + (d2 + d3), -snorm[j]);
                        if (s > bw || (s == bw && j < wj)) { bw = s; wj = j; }
                    }
                }
                #pragma unroll
                for (int off = 16; off > 0; off >>= 1) {
                    float ob = __shfl_xor_sync(0xffffffffu, bw, off);
                    int   oj = __shfl_xor_sync(0xffffffffu, wj, off);
                    if (ob > bw || (ob == bw && oj < wj)) { bw = ob; wj = oj; }
                }
                if (lane == l) jwin[h] = wj;
            }
        }

        if (tig == 0) {
            swidx[wid * 16 + gid]     = jwin[0];
            swidx[wid * 16 + 8 + gid] = jwin[1];
        }
        __syncthreads();

        // ---- output gather (from smem fp32 codebook) + exact diff
        const float4* xin = (const float4*)(x + (size_t)t * TILE_M * DIM);
        float4* oq = (float4*)(out_q + (size_t)t * TILE_M * DIM);
        const float4* cb4 = (const float4*)cbf;   // row stride CBS/4 float4
        float td = 0.f;
        #pragma unroll
        for (int it = 0; it < (TILE_M * 16) / TPB; it++) {
            int i = tid + it * TPB;
            int row = i >> 4, v = i & 15;
            float4 e = cb4[swidx[row] * (CBS / 4) + v];
            float4 xv = xin[i];
            oq[i] = e;
            float d0 = e.x - xv.x, d1 = e.y - xv.y, d2 = e.z - xv.z, d3 = e.w - xv.w;
            td = fmaf(d0, d0, td); td = fmaf(d1, d1, td);
            td = fmaf(d2, d2, td); td = fmaf(d3, d3, td);
        }
        if (tid < TILE_M) out_idx[(size_t)t * TILE_M + tid] = (float)swidx[tid];

        #pragma unroll
        for (int off = 16; off > 0; off >>= 1)
            td += __shfl_down_sync(0xffffffffu, td, off);
        if (lane == 0) sred[wid] = td;
        __syncthreads();
        if (tid == 0) {
            float s = 0.f;
            #pragma unroll
            for (int w = 0; w < NWARP; w++) s += sred[w];
            blockdiff += s;                       // fixed tile order per block
        }
        __syncthreads();
    }

    // ---- fused deterministic finalize: last block sums per-block partials
    if (tid == 0) {
        g_partials[blockIdx.x] = blockdiff;
        __threadfence();
        unsigned int prev = atomicAdd(&g_done, 1u);
        if (prev == GRIDSZ - 1) {
            float s = 0.f;
            #pragma unroll 4
            for (int i = 0; i < GRIDSZ; i++) s += g_partials[i];   // fixed order
            *out_diff = s * (1.0f / (float)((size_t)NROWS * DIM));
            g_done = 0;                           // reset for next graph replay
            __threadfence();
        }
    }
}

extern "C" void kernel_launch(void* const* d_in, const int* in_sizes, int n_in,
                              void* d_out, int out_size)
{
    const float* x     = (const float*)d_in[0];
    const float* embed = (const float*)d_in[1];

    float* out      = (float*)d_out;
    float* out_q    = out;
    float* out_diff = out + (size_t)NROWS * DIM;
    float* out_idx  = out + (size_t)NROWS * DIM + 1;

    cudaFuncSetAttribute(vq_kernel, cudaFuncAttributeMaxDynamicSharedMemorySize, SMEM_TOTAL);

    vq_kernel<<<GRIDSZ, TPB, SMEM_TOTAL>>>(x, embed, out_q, out_idx, out_diff);
}